// round 1
// baseline (speedup 1.0000x reference)
#include <cuda_runtime.h>
#include <math.h>

#define NTOK   8192      // B*S
#define DIM    512
#define DFFV   1024
#define NE     8
#define TM     128       // rows per GEMM tile
#define MAXT   16384     // 2*NTOK assignment rows
#define MAXTILES 136     // sum ceil(cnt_e/TM) <= MAXT/TM + NE

// ---------------- device scratch (no allocations allowed) ----------------
__device__ int   g_cnt[NE];
__device__ int   g_off[NE + 1];     // row offsets per expert
__device__ int   g_toff[NE + 1];    // m-tile offsets per expert
__device__ int   g_tok[NE * NTOK];  // token id per (expert, pos)
__device__ float g_wt [NE * NTOK];  // routing weight per (expert, pos)
__device__ float g_act[(size_t)MAXT * DFFV];  // 64 MB intermediate

// ---------------- K0: zero output + counters ----------------
__global__ void k_zero(float* __restrict__ out, int n) {
    if (blockIdx.x == 0 && threadIdx.x < NE) g_cnt[threadIdx.x] = 0;
    int i = blockIdx.x * blockDim.x + threadIdx.x;
    int stride = gridDim.x * blockDim.x;
    for (; i < n; i += stride) out[i] = 0.f;
}

// ---------------- K1: gating (warp per token) ----------------
__global__ __launch_bounds__(256) void k_gate(const float* __restrict__ x,
                                              const float* __restrict__ Wg,
                                              const float* __restrict__ bg) {
    __shared__ float wgs[DIM][9];  // pad to 9 -> conflict-free strided reads
    int t = threadIdx.x;
    for (int i = t; i < DIM * NE; i += 256) wgs[i >> 3][i & 7] = Wg[i];
    __syncthreads();

    int warp = t >> 5, lane = t & 31;
    int tok = blockIdx.x * 8 + warp;
    if (tok >= NTOK) return;

    float acc[NE];
#pragma unroll
    for (int e = 0; e < NE; e++) acc[e] = 0.f;

    const float* xr = x + (size_t)tok * DIM;
    for (int d = lane; d < DIM; d += 32) {
        float xv = xr[d];
#pragma unroll
        for (int e = 0; e < NE; e++) acc[e] += xv * wgs[d][e];
    }
#pragma unroll
    for (int e = 0; e < NE; e++)
#pragma unroll
        for (int o = 16; o; o >>= 1) acc[e] += __shfl_xor_sync(0xFFFFFFFFu, acc[e], o);

    if (lane == 0) {
        float lg[NE];
#pragma unroll
        for (int e = 0; e < NE; e++) lg[e] = acc[e] + bg[e];
        // top-2, ties -> lower index (matches jax.lax.top_k)
        int i1 = 0;
#pragma unroll
        for (int e = 1; e < NE; e++) if (lg[e] > lg[i1]) i1 = e;
        int i2 = (i1 == 0) ? 1 : 0;
#pragma unroll
        for (int e = 0; e < NE; e++) if (e != i1 && lg[e] > lg[i2]) i2 = e;
        float tt = expf(lg[i2] - lg[i1]);      // <= 1
        float w1 = 1.f / (1.f + tt);
        float w2 = tt / (1.f + tt);
        int p1 = atomicAdd(&g_cnt[i1], 1);
        g_tok[i1 * NTOK + p1] = tok; g_wt[i1 * NTOK + p1] = w1;
        int p2 = atomicAdd(&g_cnt[i2], 1);
        g_tok[i2 * NTOK + p2] = tok; g_wt[i2 * NTOK + p2] = w2;
    }
}

// ---------------- K2: tiny scan ----------------
__global__ void k_scan() {
    int r = 0, tt = 0;
    for (int e = 0; e < NE; e++) {
        g_off[e] = r; g_toff[e] = tt;
        r += g_cnt[e];
        tt += (g_cnt[e] + TM - 1) / TM;
    }
    g_off[NE] = r; g_toff[NE] = tt;
}

// ---------------- K3: grouped GEMM1 + SiLU*mul ----------------
// tile: TM=128 rows x 64 f-cols (128 weight cols: a-half + g-half), K=512
__global__ __launch_bounds__(256) void k_ffn1(const float* __restrict__ x,
                                              const float* __restrict__ W1,
                                              const float* __restrict__ b1) {
    int tile = blockIdx.x;
    if (tile >= g_toff[NE]) return;
    int e = 0;
    while (tile >= g_toff[e + 1]) e++;
    int mt = tile - g_toff[e];
    int cnt = g_cnt[e];
    int m0 = mt * TM;
    int f0 = blockIdx.y * 64;

    __shared__ __align__(16) float xs[16][132];   // [k][row]
    __shared__ __align__(16) float ws[16][128];   // [k][col] 0..63 a, 64..127 g
    __shared__ int stok[TM];

    int t = threadIdx.x;
    for (int r = t; r < TM; r += 256)
        stok[r] = (m0 + r < cnt) ? g_tok[e * NTOK + m0 + r] : -1;
    __syncthreads();

    int tx = t & 15, ty = t >> 4;
    float aa[8][4], ag[8][4];
#pragma unroll
    for (int i = 0; i < 8; i++)
#pragma unroll
        for (int j = 0; j < 4; j++) { aa[i][j] = 0.f; ag[i][j] = 0.f; }

    const float* w1e = W1 + (size_t)e * DIM * 2 * DFFV;

    for (int k0 = 0; k0 < DIM; k0 += 16) {
        // load X tile (gathered rows), transposed store
#pragma unroll
        for (int p = 0; p < 2; p++) {
            int u = t + 256 * p;
            int row = u >> 2, kq = u & 3;
            int tk = stok[row];
            float4 v = make_float4(0.f, 0.f, 0.f, 0.f);
            if (tk >= 0) v = *(const float4*)(x + (size_t)tk * DIM + k0 + kq * 4);
            xs[kq * 4 + 0][row] = v.x;
            xs[kq * 4 + 1][row] = v.y;
            xs[kq * 4 + 2][row] = v.z;
            xs[kq * 4 + 3][row] = v.w;
        }
        // load W1 tile: a-half cols [f0,f0+64), g-half cols [DFF+f0, ...)
#pragma unroll
        for (int p = 0; p < 2; p++) {
            int u = t + 256 * p;
            int k = u >> 5, jq = u & 31;
            int col = (jq < 16) ? (f0 + jq * 4) : (DFFV + f0 + (jq - 16) * 4);
            float4 v = *(const float4*)(w1e + (size_t)(k0 + k) * 2 * DFFV + col);
            *(float4*)&ws[k][jq * 4] = v;
        }
        __syncthreads();
#pragma unroll
        for (int k = 0; k < 16; k++) {
            float4 x0 = *(const float4*)&xs[k][ty * 8];
            float4 x1 = *(const float4*)&xs[k][ty * 8 + 4];
            float xv[8] = {x0.x, x0.y, x0.z, x0.w, x1.x, x1.y, x1.z, x1.w};
            float4 wa = *(const float4*)&ws[k][tx * 4];
            float4 wg = *(const float4*)&ws[k][64 + tx * 4];
            float wav[4] = {wa.x, wa.y, wa.z, wa.w};
            float wgv[4] = {wg.x, wg.y, wg.z, wg.w};
#pragma unroll
            for (int i = 0; i < 8; i++)
#pragma unroll
                for (int j = 0; j < 4; j++) {
                    aa[i][j] += xv[i] * wav[j];
                    ag[i][j] += xv[i] * wgv[j];
                }
        }
        __syncthreads();
    }

    // epilogue: bias + silu(a)*g -> g_act
    int off = g_off[e];
    const float* b1e = b1 + (size_t)e * 2 * DFFV;
#pragma unroll
    for (int i = 0; i < 8; i++) {
        int r = ty * 8 + i;
        if (m0 + r >= cnt) continue;
        int slot = off + m0 + r;
        float o[4];
#pragma unroll
        for (int j = 0; j < 4; j++) {
            int f = f0 + tx * 4 + j;
            float a = aa[i][j] + b1e[f];
            float g = ag[i][j] + b1e[DFFV + f];
            float s = a / (1.f + expf(-a));
            o[j] = s * g;
        }
        *(float4*)(g_act + (size_t)slot * DFFV + f0 + tx * 4) =
            make_float4(o[0], o[1], o[2], o[3]);
    }
}

// ---------------- K4: grouped GEMM2 + weighted scatter ----------------
// tile: TM=128 rows x 128 cols (two 64-col halves), K=1024
__global__ __launch_bounds__(256) void k_ffn2(const float* __restrict__ W2,
                                              const float* __restrict__ b2,
                                              float* __restrict__ out) {
    int tile = blockIdx.x;
    if (tile >= g_toff[NE]) return;
    int e = 0;
    while (tile >= g_toff[e + 1]) e++;
    int mt = tile - g_toff[e];
    int cnt = g_cnt[e];
    int m0 = mt * TM;
    int c0 = blockIdx.y * 128;

    __shared__ __align__(16) float xs[16][132];
    __shared__ __align__(16) float ws[16][128];
    __shared__ int stok[TM];
    __shared__ float swt[TM];

    int t = threadIdx.x;
    for (int r = t; r < TM; r += 256) {
        int ok = (m0 + r < cnt);
        stok[r] = ok ? g_tok[e * NTOK + m0 + r] : -1;
        swt[r]  = ok ? g_wt [e * NTOK + m0 + r] : 0.f;
    }
    __syncthreads();

    int tx = t & 15, ty = t >> 4;
    float acc[8][8];
#pragma unroll
    for (int i = 0; i < 8; i++)
#pragma unroll
        for (int j = 0; j < 8; j++) acc[i][j] = 0.f;

    const float* w2e = W2 + (size_t)e * DFFV * DIM;
    int off = g_off[e];

    for (int k0 = 0; k0 < DFFV; k0 += 16) {
        // load act rows (contiguous slots)
#pragma unroll
        for (int p = 0; p < 2; p++) {
            int u = t + 256 * p;
            int row = u >> 2, kq = u & 3;
            int slot = off + m0 + row;
            if (slot >= MAXT) slot = MAXT - 1;   // clamp OOB (discarded later)
            float4 v = *(const float4*)(g_act + (size_t)slot * DFFV + k0 + kq * 4);
            xs[kq * 4 + 0][row] = v.x;
            xs[kq * 4 + 1][row] = v.y;
            xs[kq * 4 + 2][row] = v.z;
            xs[kq * 4 + 3][row] = v.w;
        }
        // load W2 tile
#pragma unroll
        for (int p = 0; p < 2; p++) {
            int u = t + 256 * p;
            int k = u >> 5, jq = u & 31;
            int col = c0 + jq * 4;
            float4 v = *(const float4*)(w2e + (size_t)(k0 + k) * DIM + col);
            *(float4*)&ws[k][jq * 4] = v;
        }
        __syncthreads();
#pragma unroll
        for (int k = 0; k < 16; k++) {
            float4 x0 = *(const float4*)&xs[k][ty * 8];
            float4 x1 = *(const float4*)&xs[k][ty * 8 + 4];
            float xv[8] = {x0.x, x0.y, x0.z, x0.w, x1.x, x1.y, x1.z, x1.w};
            float4 w0 = *(const float4*)&ws[k][tx * 4];
            float4 w1 = *(const float4*)&ws[k][64 + tx * 4];
            float wv[8] = {w0.x, w0.y, w0.z, w0.w, w1.x, w1.y, w1.z, w1.w};
#pragma unroll
            for (int i = 0; i < 8; i++)
#pragma unroll
                for (int j = 0; j < 8; j++) acc[i][j] += xv[i] * wv[j];
        }
        __syncthreads();
    }

    // epilogue: + b2, * routing weight, atomic scatter to out
    const float* b2e = b2 + (size_t)e * DIM;
#pragma unroll
    for (int i = 0; i < 8; i++) {
        int r = ty * 8 + i;
        if (m0 + r >= cnt) continue;
        int token = stok[r];
        float wgt = swt[r];
        float* orow = out + (size_t)token * DIM;
#pragma unroll
        for (int j = 0; j < 4; j++) {
            int ca = c0 + tx * 4 + j;
            int cb = c0 + 64 + tx * 4 + j;
            atomicAdd(&orow[ca], (acc[i][j]     + b2e[ca]) * wgt);
            atomicAdd(&orow[cb], (acc[i][4 + j] + b2e[cb]) * wgt);
        }
    }
}

// ---------------- launcher ----------------
extern "C" void kernel_launch(void* const* d_in, const int* in_sizes, int n_in,
                              void* d_out, int out_size) {
    const float* x  = (const float*)d_in[0];
    const float* Wg = (const float*)d_in[1];
    const float* bg = (const float*)d_in[2];
    const float* W1 = (const float*)d_in[3];
    const float* b1 = (const float*)d_in[4];
    const float* W2 = (const float*)d_in[5];
    const float* b2 = (const float*)d_in[6];
    float* out = (float*)d_out;

    k_zero<<<1024, 256>>>(out, NTOK * DIM);
    k_gate<<<NTOK / 8, 256>>>(x, Wg, bg);
    k_scan<<<1, 1>>>();
    dim3 g1(MAXTILES, DFFV / 64);   // 136 x 16
    k_ffn1<<<g1, 256>>>(x, W1, b1);
    dim3 g2(MAXTILES, DIM / 128);   // 136 x 4
    k_ffn2<<<g2, 256>>>(W2, b2, out);
}

// round 3
// speedup vs baseline: 1.7692x; 1.7692x over previous
#include <cuda_runtime.h>
#include <cuda_bf16.h>
#include <math.h>
#include <stdint.h>

#define NTOK 8192
#define DIM 512
#define DFFV 1024
#define NE 8
#define TM 128
#define MAXT 16384
#define MAXTILES 136

// ---------------- device scratch ----------------
__device__ int   g_cnt[NE];
__device__ int   g_off[NE + 1];
__device__ int   g_toff[NE + 1];
__device__ int   g_tok[NE * NTOK];
__device__ float g_wt [NE * NTOK];
__device__ __nv_bfloat16 g_xh [(size_t)MAXT * DIM];
__device__ __nv_bfloat16 g_xl [(size_t)MAXT * DIM];
__device__ __nv_bfloat16 g_w1h[(size_t)NE * 2 * DFFV * DIM];
__device__ __nv_bfloat16 g_w1l[(size_t)NE * 2 * DFFV * DIM];
__device__ __nv_bfloat16 g_w2h[(size_t)NE * DIM * DFFV];
__device__ __nv_bfloat16 g_w2l[(size_t)NE * DIM * DFFV];
__device__ __nv_bfloat16 g_ah [(size_t)MAXT * DFFV];
__device__ __nv_bfloat16 g_al [(size_t)MAXT * DFFV];

// ---------------- helpers ----------------
__device__ __forceinline__ uint32_t smem_u32(const void* p) {
    uint32_t a;
    asm("{ .reg .u64 t; cvta.to.shared.u64 t, %1; cvt.u32.u64 %0, t; }" : "=r"(a) : "l"(p));
    return a;
}
#define CPA16(sa, ga) asm volatile("cp.async.cg.shared.global [%0], [%1], 16;"::"r"(sa),"l"(ga):"memory")
#define CPA_COMMIT()  asm volatile("cp.async.commit_group;":::"memory")
#define CPA_WAIT1()   asm volatile("cp.async.wait_group 1;":::"memory")

#define LDSM_X4(r, addr) \
    asm volatile("ldmatrix.sync.aligned.m8n8.x4.shared.b16 {%0,%1,%2,%3}, [%4];" \
        : "=r"((r)[0]), "=r"((r)[1]), "=r"((r)[2]), "=r"((r)[3]) : "r"(addr))

#define MMA_BF16(d, a, b0, b1) \
    asm volatile("mma.sync.aligned.m16n8k16.row.col.f32.bf16.bf16.f32 " \
        "{%0,%1,%2,%3},{%4,%5,%6,%7},{%8,%9},{%0,%1,%2,%3};" \
        : "+f"((d)[0]), "+f"((d)[1]), "+f"((d)[2]), "+f"((d)[3]) \
        : "r"((a)[0]), "r"((a)[1]), "r"((a)[2]), "r"((a)[3]), "r"(b0), "r"(b1))

__device__ __forceinline__ uint32_t sw64(uint32_t off) {
    return off ^ ((off >> 3) & 0x30);
}

// ---------------- K0: zero output + counters ----------------
__global__ void k_zero(float* __restrict__ out, int n) {
    if (blockIdx.x == 0 && threadIdx.x < NE) g_cnt[threadIdx.x] = 0;
    int i = blockIdx.x * blockDim.x + threadIdx.x;
    int stride = gridDim.x * blockDim.x;
    for (; i < n; i += stride) out[i] = 0.f;
}

// ---------------- K1: gating ----------------
__global__ __launch_bounds__(256) void k_gate(const float* __restrict__ x,
                                              const float* __restrict__ Wg,
                                              const float* __restrict__ bg) {
    __shared__ float wgs[DIM][9];
    int t = threadIdx.x;
    for (int i = t; i < DIM * NE; i += 256) wgs[i >> 3][i & 7] = Wg[i];
    __syncthreads();

    int warp = t >> 5, lane = t & 31;
    int tok = blockIdx.x * 8 + warp;
    if (tok >= NTOK) return;

    float acc[NE];
#pragma unroll
    for (int e = 0; e < NE; e++) acc[e] = 0.f;
    const float* xr = x + (size_t)tok * DIM;
    for (int d = lane; d < DIM; d += 32) {
        float xv = xr[d];
#pragma unroll
        for (int e = 0; e < NE; e++) acc[e] += xv * wgs[d][e];
    }
#pragma unroll
    for (int e = 0; e < NE; e++)
#pragma unroll
        for (int o = 16; o; o >>= 1) acc[e] += __shfl_xor_sync(0xFFFFFFFFu, acc[e], o);

    if (lane == 0) {
        float lg[NE];
#pragma unroll
        for (int e = 0; e < NE; e++) lg[e] = acc[e] + bg[e];
        int i1 = 0;
#pragma unroll
        for (int e = 1; e < NE; e++) if (lg[e] > lg[i1]) i1 = e;
        int i2 = (i1 == 0) ? 1 : 0;
#pragma unroll
        for (int e = 0; e < NE; e++) if (e != i1 && lg[e] > lg[i2]) i2 = e;
        float tt = expf(lg[i2] - lg[i1]);
        float w1 = 1.f / (1.f + tt);
        float w2 = tt / (1.f + tt);
        int p1 = atomicAdd(&g_cnt[i1], 1);
        g_tok[i1 * NTOK + p1] = tok; g_wt[i1 * NTOK + p1] = w1;
        int p2 = atomicAdd(&g_cnt[i2], 1);
        g_tok[i2 * NTOK + p2] = tok; g_wt[i2 * NTOK + p2] = w2;
    }
}

// ---------------- K2: scan ----------------
__global__ void k_scan() {
    int r = 0, tt = 0;
    for (int e = 0; e < NE; e++) {
        g_off[e] = r; g_toff[e] = tt;
        r += g_cnt[e];
        tt += (g_cnt[e] + TM - 1) / TM;
    }
    g_off[NE] = r; g_toff[NE] = tt;
}

// ---------------- K3: gather x -> bf16 hi/lo ----------------
__global__ __launch_bounds__(128) void k_conv_x(const float* __restrict__ x) {
    int slot = blockIdx.x;
    int e = 0;
    while (e < NE - 1 && slot >= g_off[e + 1]) e++;
    int token = g_tok[e * NTOK + (slot - g_off[e])];
    float4 v = ((const float4*)(x + (size_t)token * DIM))[threadIdx.x];
    float f[4] = {v.x, v.y, v.z, v.w};
    __nv_bfloat16 h[4], l[4];
#pragma unroll
    for (int j = 0; j < 4; j++) {
        h[j] = __float2bfloat16(f[j]);
        l[j] = __float2bfloat16(f[j] - __bfloat162float(h[j]));
    }
    *(uint2*)(g_xh + (size_t)slot * DIM + threadIdx.x * 4) = *(uint2*)h;
    *(uint2*)(g_xl + (size_t)slot * DIM + threadIdx.x * 4) = *(uint2*)l;
}

// ---------------- K4/K5: weight transpose + split ----------------
__global__ void k_conv_w1(const float* __restrict__ W1) {
    __shared__ float ts[32][33];
    int e = blockIdx.z, n0 = blockIdx.x * 32, k0 = blockIdx.y * 32;
    int tx = threadIdx.x, ty = threadIdx.y;
    const float* src = W1 + (size_t)e * DIM * 2 * DFFV;
#pragma unroll
    for (int i = 0; i < 4; i++)
        ts[ty + i * 8][tx] = src[(size_t)(k0 + ty + i * 8) * 2 * DFFV + n0 + tx];
    __syncthreads();
#pragma unroll
    for (int i = 0; i < 4; i++) {
        float v = ts[tx][ty + i * 8];
        __nv_bfloat16 h = __float2bfloat16(v);
        __nv_bfloat16 l = __float2bfloat16(v - __bfloat162float(h));
        size_t o = (size_t)e * 2 * DFFV * DIM + (size_t)(n0 + ty + i * 8) * DIM + k0 + tx;
        g_w1h[o] = h; g_w1l[o] = l;
    }
}
__global__ void k_conv_w2(const float* __restrict__ W2) {
    __shared__ float ts[32][33];
    int e = blockIdx.z, d0 = blockIdx.x * 32, f0 = blockIdx.y * 32;
    int tx = threadIdx.x, ty = threadIdx.y;
    const float* src = W2 + (size_t)e * DFFV * DIM;
#pragma unroll
    for (int i = 0; i < 4; i++)
        ts[ty + i * 8][tx] = src[(size_t)(f0 + ty + i * 8) * DIM + d0 + tx];
    __syncthreads();
#pragma unroll
    for (int i = 0; i < 4; i++) {
        float v = ts[tx][ty + i * 8];
        __nv_bfloat16 h = __float2bfloat16(v);
        __nv_bfloat16 l = __float2bfloat16(v - __bfloat162float(h));
        size_t o = (size_t)e * DIM * DFFV + (size_t)(d0 + ty + i * 8) * DFFV + f0 + tx;
        g_w2h[o] = h; g_w2l[o] = l;
    }
}

// ==================== GEMM core (mma.sync bf16 hi/lo) ====================
// tile 128x128, BK=32, 3 stages, 8 warps (2x4), warp tile 64x32
#define ST_AH 0
#define ST_AL 8192
#define ST_BH 16384
#define ST_BL 24576
#define ST_STRIDE 32768
#define NSTAGE 3

struct Frag { float acc[4][4][4]; };

__device__ __forceinline__ void compute_chunk(uint32_t sbase, int stage,
                                              int wm, int wn, int lane,
                                              float acc[4][4][4]) {
    uint32_t aOff  = sbase + stage * ST_STRIDE + ST_AH;
    uint32_t alOff = sbase + stage * ST_STRIDE + ST_AL;
    uint32_t bhOff = sbase + stage * ST_STRIDE + ST_BH;
    uint32_t blOff = sbase + stage * ST_STRIDE + ST_BL;
    int lr = lane & 15, lh = lane >> 4;
#pragma unroll
    for (int ks = 0; ks < 2; ks++) {
        uint32_t bh[8], bl[8];
#pragma unroll
        for (int jp = 0; jp < 2; jp++) {
            uint32_t o = (uint32_t)(wn * 32 + jp * 16 + lr) * 64 + ks * 32 + lh * 16;
            o = sw64(o);
            LDSM_X4(&bh[jp * 4], bhOff + o);
            LDSM_X4(&bl[jp * 4], blOff + o);
        }
#pragma unroll
        for (int i = 0; i < 4; i++) {
            uint32_t o = (uint32_t)(wm * 64 + i * 16 + lr) * 64 + ks * 32 + lh * 16;
            o = sw64(o);
            uint32_t ah[4], al[4];
            LDSM_X4(ah, aOff + o);
            LDSM_X4(al, alOff + o);
#pragma unroll
            for (int j = 0; j < 4; j++) {
                int jp = j >> 1, idx = j & 1;
                uint32_t bh0 = bh[jp * 4 + idx], bh1 = bh[jp * 4 + idx + 2];
                uint32_t bl0 = bl[jp * 4 + idx], bl1 = bl[jp * 4 + idx + 2];
                MMA_BF16(acc[i][j], ah, bh0, bh1);
                MMA_BF16(acc[i][j], ah, bl0, bl1);
                MMA_BF16(acc[i][j], al, bh0, bh1);
            }
        }
    }
}

// ---------------- K6: GEMM1 + SiLU*mul -> act hi/lo ----------------
__global__ __launch_bounds__(256, 1) void k_mm1(const float* __restrict__ b1) {
    int tile = blockIdx.x;
    if (tile >= g_toff[NE]) return;
    int e = 0;
    while (tile >= g_toff[e + 1]) e++;
    int m0 = (tile - g_toff[e]) * TM;
    int cnt = g_cnt[e];
    int off = g_off[e];
    int f0 = blockIdx.y * 64;

    extern __shared__ __align__(1024) char dsm[];
    __shared__ float sb1a[64], sb1g[64];
    uint32_t sbase = smem_u32(dsm);

    int tid = threadIdx.x, wid = tid >> 5, lane = tid & 31;
    int wm = wid >> 2, wn = wid & 3;

    if (tid < 64)       sb1a[tid] = b1[(size_t)e * 2 * DFFV + f0 + tid];
    else if (tid < 128) sb1g[tid - 64] = b1[(size_t)e * 2 * DFFV + DFFV + f0 + tid - 64];

    const __nv_bfloat16* w1h = g_w1h + (size_t)e * 2 * DFFV * DIM;
    const __nv_bfloat16* w1l = g_w1l + (size_t)e * 2 * DFFV * DIM;

    float acc[4][4][4];
#pragma unroll
    for (int i = 0; i < 4; i++)
#pragma unroll
        for (int j = 0; j < 4; j++)
#pragma unroll
            for (int q = 0; q < 4; q++) acc[i][j][q] = 0.f;

    auto load_chunk = [&](int stage, int c) {
        uint32_t base = sbase + stage * ST_STRIDE;
        int k0 = c * 32;
#pragma unroll
        for (int u = tid; u < 512; u += 256) {
            int r = u >> 2, cs = u & 3;
            uint32_t sw = sw64((uint32_t)r * 64 + cs * 16);
            int slot = off + m0 + r; if (slot > MAXT - 1) slot = MAXT - 1;
            size_t ga = (size_t)slot * DIM + k0 + cs * 8;
            CPA16(base + ST_AH + sw, g_xh + ga);
            CPA16(base + ST_AL + sw, g_xl + ga);
            int nw = (r & 1) ? (DFFV + f0 + (r >> 1)) : (f0 + (r >> 1));
            size_t gb = (size_t)nw * DIM + k0 + cs * 8;
            CPA16(base + ST_BH + sw, w1h + gb);
            CPA16(base + ST_BL + sw, w1l + gb);
        }
    };

    const int NC = DIM / 32;  // 16
    load_chunk(0, 0); CPA_COMMIT();
    load_chunk(1, 1); CPA_COMMIT();
    CPA_WAIT1();
    __syncthreads();
    for (int c = 0; c < NC; c++) {
        if (c + 2 < NC) load_chunk((c + 2) % NSTAGE, c + 2);
        CPA_COMMIT();
        compute_chunk(sbase, c % NSTAGE, wm, wn, lane, acc);
        CPA_WAIT1();
        __syncthreads();
    }

    // fuse bias + silu*mul in registers; keep v in acc[i][j][0] (row) and [2] (row+8)
#pragma unroll
    for (int i = 0; i < 4; i++)
#pragma unroll
        for (int j = 0; j < 4; j++) {
            int fl = wn * 16 + j * 4 + (lane & 3);
            float ba = sb1a[fl], bg = sb1g[fl];
            float a0 = acc[i][j][0] + ba, gg0 = acc[i][j][1] + bg;
            float a1 = acc[i][j][2] + ba, gg1 = acc[i][j][3] + bg;
            acc[i][j][0] = gg0 * a0 / (1.f + __expf(-a0));
            acc[i][j][2] = gg1 * a1 / (1.f + __expf(-a1));
        }

    // staged store: hi then lo, through smem [128][72] bf16
    __nv_bfloat16* st = (__nv_bfloat16*)dsm;
#pragma unroll
    for (int half = 0; half < 2; half++) {
#pragma unroll
        for (int i = 0; i < 4; i++) {
            int r0 = wm * 64 + i * 16 + (lane >> 2);
#pragma unroll
            for (int j = 0; j < 4; j++) {
                int fl = wn * 16 + j * 4 + (lane & 3);
                float v0 = acc[i][j][0], v1 = acc[i][j][2];
                __nv_bfloat16 h0 = __float2bfloat16(v0);
                __nv_bfloat16 h1 = __float2bfloat16(v1);
                if (half == 0) {
                    st[r0 * 72 + fl] = h0;
                    st[(r0 + 8) * 72 + fl] = h1;
                } else {
                    st[r0 * 72 + fl] = __float2bfloat16(v0 - __bfloat162float(h0));
                    st[(r0 + 8) * 72 + fl] = __float2bfloat16(v1 - __bfloat162float(h1));
                }
            }
        }
        __syncthreads();
        __nv_bfloat16* dst = half ? g_al : g_ah;
#pragma unroll
        for (int u = tid; u < 1024; u += 256) {
            int r = u >> 3, seg = u & 7;
            if (m0 + r < cnt) {
                size_t slot = (size_t)(off + m0 + r);
                *(uint4*)(dst + slot * DFFV + f0 + seg * 8) = *(uint4*)&st[r * 72 + seg * 8];
            }
        }
        __syncthreads();
    }
}

// ---------------- K7: GEMM2 + weighted atomic scatter ----------------
__global__ __launch_bounds__(256, 1) void k_mm2(const float* __restrict__ b2,
                                                float* __restrict__ out) {
    int tile = blockIdx.x;
    if (tile >= g_toff[NE]) return;
    int e = 0;
    while (tile >= g_toff[e + 1]) e++;
    int m0 = (tile - g_toff[e]) * TM;
    int cnt = g_cnt[e];
    int off = g_off[e];
    int c0 = blockIdx.y * 128;

    extern __shared__ __align__(1024) char dsm[];
    __shared__ float sb2[128];
    __shared__ int   s_tok[128];
    __shared__ float s_wt[128];
    uint32_t sbase = smem_u32(dsm);

    int tid = threadIdx.x, wid = tid >> 5, lane = tid & 31;
    int wm = wid >> 2, wn = wid & 3;

    if (tid < 128) {
        sb2[tid] = b2[(size_t)e * DIM + c0 + tid];
        int ok = (m0 + tid) < cnt;
        s_tok[tid] = ok ? g_tok[e * NTOK + m0 + tid] : -1;
        s_wt[tid]  = ok ? g_wt [e * NTOK + m0 + tid] : 0.f;
    }

    const __nv_bfloat16* w2h = g_w2h + (size_t)e * DIM * DFFV;
    const __nv_bfloat16* w2l = g_w2l + (size_t)e * DIM * DFFV;

    float acc[4][4][4];
#pragma unroll
    for (int i = 0; i < 4; i++)
#pragma unroll
        for (int j = 0; j < 4; j++)
#pragma unroll
            for (int q = 0; q < 4; q++) acc[i][j][q] = 0.f;

    auto load_chunk = [&](int stage, int c) {
        uint32_t base = sbase + stage * ST_STRIDE;
        int k0 = c * 32;
#pragma unroll
        for (int u = tid; u < 512; u += 256) {
            int r = u >> 2, cs = u & 3;
            uint32_t sw = sw64((uint32_t)r * 64 + cs * 16);
            int slot = off + m0 + r; if (slot > MAXT - 1) slot = MAXT - 1;
            size_t ga = (size_t)slot * DFFV + k0 + cs * 8;
            CPA16(base + ST_AH + sw, g_ah + ga);
            CPA16(base + ST_AL + sw, g_al + ga);
            size_t gb = (size_t)(c0 + r) * DFFV + k0 + cs * 8;
            CPA16(base + ST_BH + sw, w2h + gb);
            CPA16(base + ST_BL + sw, w2l + gb);
        }
    };

    const int NC = DFFV / 32;  // 32
    load_chunk(0, 0); CPA_COMMIT();
    load_chunk(1, 1); CPA_COMMIT();
    CPA_WAIT1();
    __syncthreads();
    for (int c = 0; c < NC; c++) {
        if (c + 2 < NC) load_chunk((c + 2) % NSTAGE, c + 2);
        CPA_COMMIT();
        compute_chunk(sbase, c % NSTAGE, wm, wn, lane, acc);
        CPA_WAIT1();
        __syncthreads();
    }

    // epilogue: bias + routing weight + atomicAdd (2 adds per out elem total)
#pragma unroll
    for (int i = 0; i < 4; i++) {
        int r0 = wm * 64 + i * 16 + (lane >> 2);
        int r1 = r0 + 8;
        int tok0 = s_tok[r0], tok1 = s_tok[r1];
        float wt0 = s_wt[r0], wt1 = s_wt[r1];
#pragma unroll
        for (int j = 0; j < 4; j++) {
            int nl = wn * 32 + j * 8 + (lane & 3) * 2;
            float bA = sb2[nl], bB = sb2[nl + 1];
            if (tok0 >= 0) {
                float* orow = out + (size_t)tok0 * DIM + c0 + nl;
                atomicAdd(orow,     (acc[i][j][0] + bA) * wt0);
                atomicAdd(orow + 1, (acc[i][j][1] + bB) * wt0);
            }
            if (tok1 >= 0) {
                float* orow = out + (size_t)tok1 * DIM + c0 + nl;
                atomicAdd(orow,     (acc[i][j][2] + bA) * wt1);
                atomicAdd(orow + 1, (acc[i][j][3] + bB) * wt1);
            }
        }
    }
}

// ---------------- launcher ----------------
extern "C" void kernel_launch(void* const* d_in, const int* in_sizes, int n_in,
                              void* d_out, int out_size) {
    const float* x  = (const float*)d_in[0];
    const float* Wg = (const float*)d_in[1];
    const float* bg = (const float*)d_in[2];
    const float* W1 = (const float*)d_in[3];
    const float* b1 = (const float*)d_in[4];
    const float* W2 = (const float*)d_in[5];
    const float* b2 = (const float*)d_in[6];
    float* out = (float*)d_out;

    const int SMEM = NSTAGE * ST_STRIDE;  // 96 KB
    cudaFuncSetAttribute(k_mm1, cudaFuncAttributeMaxDynamicSharedMemorySize, SMEM);
    cudaFuncSetAttribute(k_mm2, cudaFuncAttributeMaxDynamicSharedMemorySize, SMEM);

    k_zero<<<1024, 256>>>(out, NTOK * DIM);
    k_conv_w1<<<dim3(64, 16, NE), dim3(32, 8)>>>(W1);
    k_conv_w2<<<dim3(16, 32, NE), dim3(32, 8)>>>(W2);
    k_gate<<<NTOK / 8, 256>>>(x, Wg, bg);
    k_scan<<<1, 1>>>();
    k_conv_x<<<MAXT, 128>>>(x);
    k_mm1<<<dim3(MAXTILES, DFFV / 64), 256, SMEM>>>(b1);
    k_mm2<<<dim3(MAXTILES, DIM / 128), 256, SMEM>>>(b2, out);
}

// round 7
// speedup vs baseline: 2.8859x; 1.6312x over previous
#include <cuda_runtime.h>
#include <cuda_fp16.h>
#include <math.h>
#include <stdint.h>

#define NTOK 8192
#define DIM 512
#define DFFV 1024
#define NE 8
#define TM 128
#define MAXT 16384
#define MAXTILES 136

// ---------------- device scratch ----------------
__device__ int   g_cnt[NE];
__device__ int   g_off[NE + 1];
__device__ int   g_toff[NE + 1];
__device__ int   g_tok[NE * NTOK];
__device__ float g_wt [NE * NTOK];
__device__ __half g_x  [(size_t)MAXT * DIM];               // gathered x, fp16 (single)
__device__ __half g_w1h[(size_t)NE * 2 * DFFV * DIM];      // W1^T hi
__device__ __half g_w1l[(size_t)NE * 2 * DFFV * DIM];      // W1^T lo
__device__ __half g_w2h[(size_t)NE * DIM * DFFV];          // W2^T hi
__device__ __half g_w2l[(size_t)NE * DIM * DFFV];          // W2^T lo
__device__ __half g_a  [(size_t)MAXT * DFFV];              // act, fp16 (single)

// ---------------- helpers ----------------
__device__ __forceinline__ uint32_t smem_u32(const void* p) {
    uint32_t a;
    asm("{ .reg .u64 t; cvta.to.shared.u64 t, %1; cvt.u32.u64 %0, t; }" : "=r"(a) : "l"(p));
    return a;
}
#define CPA16(sa, ga) asm volatile("cp.async.cg.shared.global [%0], [%1], 16;"::"r"(sa),"l"(ga):"memory")
#define CPA_COMMIT()  asm volatile("cp.async.commit_group;":::"memory")
#define CPA_WAIT1()   asm volatile("cp.async.wait_group 1;":::"memory")

#define LDSM_X4(r, addr) \
    asm volatile("ldmatrix.sync.aligned.m8n8.x4.shared.b16 {%0,%1,%2,%3}, [%4];" \
        : "=r"((r)[0]), "=r"((r)[1]), "=r"((r)[2]), "=r"((r)[3]) : "r"(addr))

#define MMA_F16(d, a, b0, b1) \
    asm volatile("mma.sync.aligned.m16n8k16.row.col.f32.f16.f16.f32 " \
        "{%0,%1,%2,%3},{%4,%5,%6,%7},{%8,%9},{%0,%1,%2,%3};" \
        : "+f"((d)[0]), "+f"((d)[1]), "+f"((d)[2]), "+f"((d)[3]) \
        : "r"((a)[0]), "r"((a)[1]), "r"((a)[2]), "r"((a)[3]), "r"(b0), "r"(b1))

__device__ __forceinline__ uint32_t sw64(uint32_t off) {
    return off ^ ((off >> 3) & 0x30);
}

// ---------------- K0: zero output + counters ----------------
__global__ void k_zero(float* __restrict__ out, int n) {
    if (blockIdx.x == 0 && threadIdx.x < NE) g_cnt[threadIdx.x] = 0;
    int i = blockIdx.x * blockDim.x + threadIdx.x;
    int stride = gridDim.x * blockDim.x;
    for (; i < n; i += stride) out[i] = 0.f;
}

// ---------------- K1: gating (warp per token, float4 loads) ----------------
__global__ __launch_bounds__(256) void k_gate(const float* __restrict__ x,
                                              const float* __restrict__ Wg,
                                              const float* __restrict__ bg) {
    __shared__ float wgs[DIM][9];
    int t = threadIdx.x;
    for (int i = t; i < DIM * NE; i += 256) wgs[i >> 3][i & 7] = Wg[i];
    __syncthreads();

    int warp = t >> 5, lane = t & 31;
    int tok = blockIdx.x * 8 + warp;
    if (tok >= NTOK) return;

    float acc[NE];
#pragma unroll
    for (int e = 0; e < NE; e++) acc[e] = 0.f;
    const float4* xr = (const float4*)(x + (size_t)tok * DIM);
#pragma unroll 4
    for (int d4 = lane; d4 < 128; d4 += 32) {
        float4 v = xr[d4];
        int d = d4 * 4;
#pragma unroll
        for (int e = 0; e < NE; e++)
            acc[e] += v.x * wgs[d][e] + v.y * wgs[d + 1][e]
                    + v.z * wgs[d + 2][e] + v.w * wgs[d + 3][e];
    }
#pragma unroll
    for (int e = 0; e < NE; e++)
#pragma unroll
        for (int o = 16; o; o >>= 1) acc[e] += __shfl_xor_sync(0xFFFFFFFFu, acc[e], o);

    if (lane == 0) {
        float lg[NE];
#pragma unroll
        for (int e = 0; e < NE; e++) lg[e] = acc[e] + bg[e];
        int i1 = 0;
#pragma unroll
        for (int e = 1; e < NE; e++) if (lg[e] > lg[i1]) i1 = e;
        int i2 = (i1 == 0) ? 1 : 0;
#pragma unroll
        for (int e = 0; e < NE; e++) if (e != i1 && lg[e] > lg[i2]) i2 = e;
        float tt = expf(lg[i2] - lg[i1]);
        float w1 = 1.f / (1.f + tt);
        float w2 = tt / (1.f + tt);
        int p1 = atomicAdd(&g_cnt[i1], 1);
        g_tok[i1 * NTOK + p1] = tok; g_wt[i1 * NTOK + p1] = w1;
        int p2 = atomicAdd(&g_cnt[i2], 1);
        g_tok[i2 * NTOK + p2] = tok; g_wt[i2 * NTOK + p2] = w2;
    }
}

// ---------------- K2: scan ----------------
__global__ void k_scan() {
    int r = 0, tt = 0;
    for (int e = 0; e < NE; e++) {
        g_off[e] = r; g_toff[e] = tt;
        r += g_cnt[e];
        tt += (g_cnt[e] + TM - 1) / TM;
    }
    g_off[NE] = r; g_toff[NE] = tt;
}

// ---------------- K3: gather x -> fp16 ----------------
__global__ __launch_bounds__(128) void k_conv_x(const float* __restrict__ x) {
    int slot = blockIdx.x;
    int e = 0;
    while (e < NE - 1 && slot >= g_off[e + 1]) e++;
    int token = g_tok[e * NTOK + (slot - g_off[e])];
    float4 v = ((const float4*)(x + (size_t)token * DIM))[threadIdx.x];
    __half h[4] = {__float2half(v.x), __float2half(v.y),
                   __float2half(v.z), __float2half(v.w)};
    *(uint2*)(g_x + (size_t)slot * DIM + threadIdx.x * 4) = *(uint2*)h;
}

// ---------------- K4/K5: weight transpose + fp16 hi/lo split ----------------
__global__ void k_conv_w1(const float* __restrict__ W1) {
    __shared__ float ts[32][33];
    int e = blockIdx.z, n0 = blockIdx.x * 32, k0 = blockIdx.y * 32;
    int tx = threadIdx.x, ty = threadIdx.y;
    const float* src = W1 + (size_t)e * DIM * 2 * DFFV;
#pragma unroll
    for (int i = 0; i < 4; i++)
        ts[ty + i * 8][tx] = src[(size_t)(k0 + ty + i * 8) * 2 * DFFV + n0 + tx];
    __syncthreads();
#pragma unroll
    for (int i = 0; i < 4; i++) {
        float v = ts[tx][ty + i * 8];
        __half h = __float2half(v);
        __half l = __float2half(v - __half2float(h));
        size_t o = (size_t)e * 2 * DFFV * DIM + (size_t)(n0 + ty + i * 8) * DIM + k0 + tx;
        g_w1h[o] = h; g_w1l[o] = l;
    }
}
__global__ void k_conv_w2(const float* __restrict__ W2) {
    __shared__ float ts[32][33];
    int e = blockIdx.z, d0 = blockIdx.x * 32, f0 = blockIdx.y * 32;
    int tx = threadIdx.x, ty = threadIdx.y;
    const float* src = W2 + (size_t)e * DFFV * DIM;
#pragma unroll
    for (int i = 0; i < 4; i++)
        ts[ty + i * 8][tx] = src[(size_t)(f0 + ty + i * 8) * DIM + d0 + tx];
    __syncthreads();
#pragma unroll
    for (int i = 0; i < 4; i++) {
        float v = ts[tx][ty + i * 8];
        __half h = __float2half(v);
        __half l = __float2half(v - __half2float(h));
        size_t o = (size_t)e * DIM * DFFV + (size_t)(d0 + ty + i * 8) * DFFV + f0 + tx;
        g_w2h[o] = h; g_w2l[o] = l;
    }
}

// ==================== GEMM core (mma.sync fp16, 2-term B split) ====================
// tile 128x128, BK=32, 3 stages, 8 warps (2x4), warp tile 64x32
#define ST_A  0
#define ST_BH 8192
#define ST_BL 16384
#define ST_STRIDE 24576
#define NSTAGE 3

__device__ __forceinline__ void compute_chunk(uint32_t sbase, int stage,
                                              int wm, int wn, int lane,
                                              float acc[4][4][4]) {
    uint32_t aOff  = sbase + stage * ST_STRIDE + ST_A;
    uint32_t bhOff = sbase + stage * ST_STRIDE + ST_BH;
    uint32_t blOff = sbase + stage * ST_STRIDE + ST_BL;
    int lr = lane & 15, lh = lane >> 4;
#pragma unroll
    for (int ks = 0; ks < 2; ks++) {
        uint32_t bh[8], bl[8];
#pragma unroll
        for (int jp = 0; jp < 2; jp++) {
            uint32_t o = sw64((uint32_t)(wn * 32 + jp * 16 + lr) * 64 + ks * 32 + lh * 16);
            LDSM_X4(&bh[jp * 4], bhOff + o);
            LDSM_X4(&bl[jp * 4], blOff + o);
        }
#pragma unroll
        for (int i = 0; i < 4; i++) {
            uint32_t o = sw64((uint32_t)(wm * 64 + i * 16 + lr) * 64 + ks * 32 + lh * 16);
            uint32_t af[4];
            LDSM_X4(af, aOff + o);
#pragma unroll
            for (int j = 0; j < 4; j++) {
                int jp = j >> 1, idx = j & 1;
                MMA_F16(acc[i][j], af, bh[jp * 4 + idx], bh[jp * 4 + idx + 2]);
                MMA_F16(acc[i][j], af, bl[jp * 4 + idx], bl[jp * 4 + idx + 2]);
            }
        }
    }
}

// ---------------- K6: GEMM1 + SiLU*mul -> act fp16 ----------------
__global__ __launch_bounds__(256, 2) void k_mm1(const float* __restrict__ b1) {
    int tile = blockIdx.x;
    if (tile >= g_toff[NE]) return;
    int e = 0;
    while (tile >= g_toff[e + 1]) e++;
    int m0 = (tile - g_toff[e]) * TM;
    int cnt = g_cnt[e];
    int off = g_off[e];
    int f0 = blockIdx.y * 64;

    extern __shared__ __align__(1024) char dsm[];
    __shared__ float sb1a[64], sb1g[64];
    uint32_t sbase = smem_u32(dsm);

    int tid = threadIdx.x, wid = tid >> 5, lane = tid & 31;
    int wm = wid >> 2, wn = wid & 3;

    if (tid < 64)       sb1a[tid] = b1[(size_t)e * 2 * DFFV + f0 + tid];
    else if (tid < 128) sb1g[tid - 64] = b1[(size_t)e * 2 * DFFV + DFFV + f0 + tid - 64];

    const __half* w1h = g_w1h + (size_t)e * 2 * DFFV * DIM;
    const __half* w1l = g_w1l + (size_t)e * 2 * DFFV * DIM;

    float acc[4][4][4];
#pragma unroll
    for (int i = 0; i < 4; i++)
#pragma unroll
        for (int j = 0; j < 4; j++)
#pragma unroll
            for (int q = 0; q < 4; q++) acc[i][j][q] = 0.f;

    auto load_chunk = [&](int stage, int c) {
        uint32_t base = sbase + stage * ST_STRIDE;
        int k0 = c * 32;
#pragma unroll
        for (int u = tid; u < 512; u += 256) {
            int r = u >> 2, cs = u & 3;
            uint32_t sw = sw64((uint32_t)r * 64 + cs * 16);
            int slot = off + m0 + r; if (slot > MAXT - 1) slot = MAXT - 1;
            CPA16(base + ST_A + sw, g_x + (size_t)slot * DIM + k0 + cs * 8);
            int nw = (r & 1) ? (DFFV + f0 + (r >> 1)) : (f0 + (r >> 1));
            size_t gb = (size_t)nw * DIM + k0 + cs * 8;
            CPA16(base + ST_BH + sw, w1h + gb);
            CPA16(base + ST_BL + sw, w1l + gb);
        }
    };

    const int NC = DIM / 32;  // 16
    load_chunk(0, 0); CPA_COMMIT();
    load_chunk(1, 1); CPA_COMMIT();
    CPA_WAIT1();
    __syncthreads();
    for (int c = 0; c < NC; c++) {
        if (c + 2 < NC) load_chunk((c + 2) % NSTAGE, c + 2);
        CPA_COMMIT();
        compute_chunk(sbase, c % NSTAGE, wm, wn, lane, acc);
        CPA_WAIT1();
        __syncthreads();
    }

    // fuse bias + silu*mul in registers
#pragma unroll
    for (int i = 0; i < 4; i++)
#pragma unroll
        for (int j = 0; j < 4; j++) {
            int fl = wn * 16 + j * 4 + (lane & 3);
            float ba = sb1a[fl], bg = sb1g[fl];
            float a0 = acc[i][j][0] + ba, gg0 = acc[i][j][1] + bg;
            float a1 = acc[i][j][2] + ba, gg1 = acc[i][j][3] + bg;
            acc[i][j][0] = gg0 * a0 / (1.f + __expf(-a0));
            acc[i][j][2] = gg1 * a1 / (1.f + __expf(-a1));
        }

    // staged store through smem [128][72] halfs, coalesced 16B writes
    __half* st = (__half*)dsm;
#pragma unroll
    for (int i = 0; i < 4; i++) {
        int r0 = wm * 64 + i * 16 + (lane >> 2);
#pragma unroll
        for (int j = 0; j < 4; j++) {
            int fl = wn * 16 + j * 4 + (lane & 3);
            st[r0 * 72 + fl] = __float2half(acc[i][j][0]);
            st[(r0 + 8) * 72 + fl] = __float2half(acc[i][j][2]);
        }
    }
    __syncthreads();
    // FIX (R5 bug): 16-byte stores (uint4 = 8 halves) so all 64 f-cols per row
    // are written; the uint2 version covered only half of g_a.
#pragma unroll
    for (int u = tid; u < 1024; u += 256) {
        int r = u >> 3, seg = u & 7;
        if (m0 + r < cnt) {
            size_t slot = (size_t)(off + m0 + r);
            *(uint4*)(g_a + slot * DFFV + f0 + seg * 8) = *(uint4*)&st[r * 72 + seg * 8];
        }
    }
}

// ---------------- K7: GEMM2 + weighted atomic scatter ----------------
__global__ __launch_bounds__(256, 2) void k_mm2(const float* __restrict__ b2,
                                                float* __restrict__ out) {
    int tile = blockIdx.x;
    if (tile >= g_toff[NE]) return;
    int e = 0;
    while (tile >= g_toff[e + 1]) e++;
    int m0 = (tile - g_toff[e]) * TM;
    int cnt = g_cnt[e];
    int off = g_off[e];
    int c0 = blockIdx.y * 128;

    extern __shared__ __align__(1024) char dsm[];
    __shared__ float sb2[128];
    __shared__ int   s_tok[128];
    __shared__ float s_wt[128];
    uint32_t sbase = smem_u32(dsm);

    int tid = threadIdx.x, wid = tid >> 5, lane = tid & 31;
    int wm = wid >> 2, wn = wid & 3;

    if (tid < 128) {
        sb2[tid] = b2[(size_t)e * DIM + c0 + tid];
        int ok = (m0 + tid) < cnt;
        s_tok[tid] = ok ? g_tok[e * NTOK + m0 + tid] : -1;
        s_wt[tid]  = ok ? g_wt [e * NTOK + m0 + tid] : 0.f;
    }

    const __half* w2h = g_w2h + (size_t)e * DIM * DFFV;
    const __half* w2l = g_w2l + (size_t)e * DIM * DFFV;

    float acc[4][4][4];
#pragma unroll
    for (int i = 0; i < 4; i++)
#pragma unroll
        for (int j = 0; j < 4; j++)
#pragma unroll
            for (int q = 0; q < 4; q++) acc[i][j][q] = 0.f;

    auto load_chunk = [&](int stage, int c) {
        uint32_t base = sbase + stage * ST_STRIDE;
        int k0 = c * 32;
#pragma unroll
        for (int u = tid; u < 512; u += 256) {
            int r = u >> 2, cs = u & 3;
            uint32_t sw = sw64((uint32_t)r * 64 + cs * 16);
            int slot = off + m0 + r; if (slot > MAXT - 1) slot = MAXT - 1;
            CPA16(base + ST_A + sw, g_a + (size_t)slot * DFFV + k0 + cs * 8);
            size_t gb = (size_t)(c0 + r) * DFFV + k0 + cs * 8;
            CPA16(base + ST_BH + sw, w2h + gb);
            CPA16(base + ST_BL + sw, w2l + gb);
        }
    };

    const int NC = DFFV / 32;  // 32
    load_chunk(0, 0); CPA_COMMIT();
    load_chunk(1, 1); CPA_COMMIT();
    CPA_WAIT1();
    __syncthreads();
    for (int c = 0; c < NC; c++) {
        if (c + 2 < NC) load_chunk((c + 2) % NSTAGE, c + 2);
        CPA_COMMIT();
        compute_chunk(sbase, c % NSTAGE, wm, wn, lane, acc);
        CPA_WAIT1();
        __syncthreads();
    }

    // epilogue: bias + routing weight + atomicAdd (2 adds per out elem total)
#pragma unroll
    for (int i = 0; i < 4; i++) {
        int r0 = wm * 64 + i * 16 + (lane >> 2);
        int r1 = r0 + 8;
        int tok0 = s_tok[r0], tok1 = s_tok[r1];
        float wt0 = s_wt[r0], wt1 = s_wt[r1];
#pragma unroll
        for (int j = 0; j < 4; j++) {
            int nl = wn * 32 + j * 8 + (lane & 3) * 2;
            float bA = sb2[nl], bB = sb2[nl + 1];
            if (tok0 >= 0) {
                float* orow = out + (size_t)tok0 * DIM + c0 + nl;
                atomicAdd(orow,     (acc[i][j][0] + bA) * wt0);
                atomicAdd(orow + 1, (acc[i][j][1] + bB) * wt0);
            }
            if (tok1 >= 0) {
                float* orow = out + (size_t)tok1 * DIM + c0 + nl;
                atomicAdd(orow,     (acc[i][j][2] + bA) * wt1);
                atomicAdd(orow + 1, (acc[i][j][3] + bB) * wt1);
            }
        }
    }
}

// ---------------- launcher ----------------
extern "C" void kernel_launch(void* const* d_in, const int* in_sizes, int n_in,
                              void* d_out, int out_size) {
    const float* x  = (const float*)d_in[0];
    const float* Wg = (const float*)d_in[1];
    const float* bg = (const float*)d_in[2];
    const float* W1 = (const float*)d_in[3];
    const float* b1 = (const float*)d_in[4];
    const float* W2 = (const float*)d_in[5];
    const float* b2 = (const float*)d_in[6];
    float* out = (float*)d_out;

    const int SMEM = NSTAGE * ST_STRIDE;  // 72 KB
    cudaFuncSetAttribute(k_mm1, cudaFuncAttributeMaxDynamicSharedMemorySize, SMEM);
    cudaFuncSetAttribute(k_mm2, cudaFuncAttributeMaxDynamicSharedMemorySize, SMEM);

    k_zero<<<1024, 256>>>(out, NTOK * DIM);
    k_conv_w1<<<dim3(64, 16, NE), dim3(32, 8)>>>(W1);
    k_conv_w2<<<dim3(16, 32, NE), dim3(32, 8)>>>(W2);
    k_gate<<<NTOK / 8, 256>>>(x, Wg, bg);
    k_scan<<<1, 1>>>();
    k_conv_x<<<MAXT, 128>>>(x);
    k_mm1<<<dim3(MAXTILES, DFFV / 64), 256, SMEM>>>(b1);
    k_mm2<<<dim3(MAXTILES, DIM / 128), 256, SMEM>>>(b2, out);
}

// round 9
// speedup vs baseline: 3.3888x; 1.1743x over previous
#include <cuda_runtime.h>
#include <cuda_fp16.h>
#include <math.h>
#include <stdint.h>

#define NTOK 8192
#define DIM 512
#define DFFV 1024
#define NE 8
#define TM 128
#define MAXTILES 136

// ---------------- device scratch ----------------
// per-assignment arrays indexed by id = e*NTOK + pos (no scan offsets needed)
__device__ int   g_cnt[NE];
__device__ int   g_toff[NE + 1];
__device__ int   g_pair[2 * NTOK];        // token -> (id1, id2)
__device__ float g_wt  [2 * NTOK];        // token -> (w1, w2)
__device__ __half g_x  [(size_t)NE * NTOK * DIM];       // gathered x fp16
__device__ __half g_w1h[(size_t)NE * 2 * DFFV * DIM];   // W1^T hi
__device__ __half g_w1l[(size_t)NE * 2 * DFFV * DIM];   // W1^T lo
__device__ __half g_w2 [(size_t)NE * DIM * DFFV];       // W2^T (single fp16)
__device__ __half g_a  [(size_t)NE * NTOK * DFFV];      // act fp16
__device__ float  g_o  [(size_t)NE * NTOK * DIM];       // raw GEMM2 out

// ---------------- helpers ----------------
__device__ __forceinline__ uint32_t smem_u32(const void* p) {
    uint32_t a;
    asm("{ .reg .u64 t; cvta.to.shared.u64 t, %1; cvt.u32.u64 %0, t; }" : "=r"(a) : "l"(p));
    return a;
}
#define CPA16(sa, ga) asm volatile("cp.async.cg.shared.global [%0], [%1], 16;"::"r"(sa),"l"(ga):"memory")
#define CPA_COMMIT()  asm volatile("cp.async.commit_group;":::"memory")
#define CPA_WAIT1()   asm volatile("cp.async.wait_group 1;":::"memory")

#define LDSM_X4(r, addr) \
    asm volatile("ldmatrix.sync.aligned.m8n8.x4.shared.b16 {%0,%1,%2,%3}, [%4];" \
        : "=r"((r)[0]), "=r"((r)[1]), "=r"((r)[2]), "=r"((r)[3]) : "r"(addr))

#define MMA_F16(d, a, b0, b1) \
    asm volatile("mma.sync.aligned.m16n8k16.row.col.f32.f16.f16.f32 " \
        "{%0,%1,%2,%3},{%4,%5,%6,%7},{%8,%9},{%0,%1,%2,%3};" \
        : "+f"((d)[0]), "+f"((d)[1]), "+f"((d)[2]), "+f"((d)[3]) \
        : "r"((a)[0]), "r"((a)[1]), "r"((a)[2]), "r"((a)[3]), "r"(b0), "r"(b1))

__device__ __forceinline__ uint32_t sw64(uint32_t off) {
    return off ^ ((off >> 3) & 0x30);
}

// ---------------- K0: zero counters ----------------
__global__ void k_zero() {
    if (threadIdx.x < NE) g_cnt[threadIdx.x] = 0;
}

// ---------------- K1: gating + fused x->fp16 scatter ----------------
__global__ __launch_bounds__(256) void k_gate(const float* __restrict__ x,
                                              const float* __restrict__ Wg,
                                              const float* __restrict__ bg) {
    __shared__ float wgsT[NE][DIM];   // transposed: conflict-free LDS.128
    int t = threadIdx.x;
    for (int i = t; i < DIM * NE; i += 256) wgsT[i & 7][i >> 3] = Wg[i];
    __syncthreads();

    int warp = t >> 5, lane = t & 31;
    int tok = blockIdx.x * 8 + warp;

    float acc[NE];
#pragma unroll
    for (int e = 0; e < NE; e++) acc[e] = 0.f;
    const float4* xr = (const float4*)(x + (size_t)tok * DIM);
    float4 xv[4];
#pragma unroll
    for (int j = 0; j < 4; j++) {
        xv[j] = xr[lane + j * 32];
        int d = (lane + j * 32) * 4;
#pragma unroll
        for (int e = 0; e < NE; e++) {
            float4 w = *(const float4*)&wgsT[e][d];
            acc[e] += xv[j].x * w.x + xv[j].y * w.y + xv[j].z * w.z + xv[j].w * w.w;
        }
    }
#pragma unroll
    for (int e = 0; e < NE; e++)
#pragma unroll
        for (int o = 16; o; o >>= 1) acc[e] += __shfl_xor_sync(0xFFFFFFFFu, acc[e], o);

    int id1 = 0, id2 = 0;
    if (lane == 0) {
        float lg[NE];
#pragma unroll
        for (int e = 0; e < NE; e++) lg[e] = acc[e] + bg[e];
        int i1 = 0;
#pragma unroll
        for (int e = 1; e < NE; e++) if (lg[e] > lg[i1]) i1 = e;
        int i2 = (i1 == 0) ? 1 : 0;
#pragma unroll
        for (int e = 0; e < NE; e++) if (e != i1 && lg[e] > lg[i2]) i2 = e;
        float tt = expf(lg[i2] - lg[i1]);
        float w1 = 1.f / (1.f + tt);
        float w2 = tt / (1.f + tt);
        int p1 = atomicAdd(&g_cnt[i1], 1);
        int p2 = atomicAdd(&g_cnt[i2], 1);
        id1 = i1 * NTOK + p1;
        id2 = i2 * NTOK + p2;
        g_pair[2 * tok] = id1; g_pair[2 * tok + 1] = id2;
        g_wt[2 * tok] = w1;    g_wt[2 * tok + 1] = w2;
    }
    id1 = __shfl_sync(0xFFFFFFFFu, id1, 0);
    id2 = __shfl_sync(0xFFFFFFFFu, id2, 0);

    // fused fp16 conversion + scatter to both expert rows (x still in regs)
#pragma unroll
    for (int j = 0; j < 4; j++) {
        __half h[4] = {__float2half(xv[j].x), __float2half(xv[j].y),
                       __float2half(xv[j].z), __float2half(xv[j].w)};
        int c = (lane + j * 32) * 4;
        *(uint2*)(g_x + (size_t)id1 * DIM + c) = *(uint2*)h;
        *(uint2*)(g_x + (size_t)id2 * DIM + c) = *(uint2*)h;
    }
}

// ---------------- K2: tile scan ----------------
__global__ void k_scan() {
    int tt = 0;
    for (int e = 0; e < NE; e++) {
        g_toff[e] = tt;
        tt += (g_cnt[e] + TM - 1) / TM;
    }
    g_toff[NE] = tt;
}

// ---------------- K3/K4: weight transpose + fp16 (W1 hi/lo, W2 single) ----------------
__global__ void k_conv_w1(const float* __restrict__ W1) {
    __shared__ float ts[32][33];
    int e = blockIdx.z, n0 = blockIdx.x * 32, k0 = blockIdx.y * 32;
    int tx = threadIdx.x, ty = threadIdx.y;
    const float* src = W1 + (size_t)e * DIM * 2 * DFFV;
#pragma unroll
    for (int i = 0; i < 4; i++)
        ts[ty + i * 8][tx] = src[(size_t)(k0 + ty + i * 8) * 2 * DFFV + n0 + tx];
    __syncthreads();
#pragma unroll
    for (int i = 0; i < 4; i++) {
        float v = ts[tx][ty + i * 8];
        __half h = __float2half(v);
        __half l = __float2half(v - __half2float(h));
        size_t o = (size_t)e * 2 * DFFV * DIM + (size_t)(n0 + ty + i * 8) * DIM + k0 + tx;
        g_w1h[o] = h; g_w1l[o] = l;
    }
}
__global__ void k_conv_w2(const float* __restrict__ W2) {
    __shared__ float ts[32][33];
    int e = blockIdx.z, d0 = blockIdx.x * 32, f0 = blockIdx.y * 32;
    int tx = threadIdx.x, ty = threadIdx.y;
    const float* src = W2 + (size_t)e * DFFV * DIM;
#pragma unroll
    for (int i = 0; i < 4; i++)
        ts[ty + i * 8][tx] = src[(size_t)(f0 + ty + i * 8) * DIM + d0 + tx];
    __syncthreads();
#pragma unroll
    for (int i = 0; i < 4; i++) {
        float v = ts[tx][ty + i * 8];
        size_t o = (size_t)e * DIM * DFFV + (size_t)(d0 + ty + i * 8) * DFFV + f0 + tx;
        g_w2[o] = __float2half(v);
    }
}

// ==================== GEMM cores ====================
// mm1: tile 128x128, BK=32, A single + B hi/lo; mm2: A single + B single
#define ST_A  0
#define ST_BH 8192
#define ST_BL 16384
#define ST1_STRIDE 24576
#define ST2_STRIDE 16384
#define NSTAGE 3

__device__ __forceinline__ void compute_dual(uint32_t sbase, int stage,
                                             int wm, int wn, int lane,
                                             float acc[4][4][4]) {
    uint32_t aOff  = sbase + stage * ST1_STRIDE + ST_A;
    uint32_t bhOff = sbase + stage * ST1_STRIDE + ST_BH;
    uint32_t blOff = sbase + stage * ST1_STRIDE + ST_BL;
    int lr = lane & 15, lh = lane >> 4;
#pragma unroll
    for (int ks = 0; ks < 2; ks++) {
        uint32_t bh[8], bl[8];
#pragma unroll
        for (int jp = 0; jp < 2; jp++) {
            uint32_t o = sw64((uint32_t)(wn * 32 + jp * 16 + lr) * 64 + ks * 32 + lh * 16);
            LDSM_X4(&bh[jp * 4], bhOff + o);
            LDSM_X4(&bl[jp * 4], blOff + o);
        }
#pragma unroll
        for (int i = 0; i < 4; i++) {
            uint32_t o = sw64((uint32_t)(wm * 64 + i * 16 + lr) * 64 + ks * 32 + lh * 16);
            uint32_t af[4];
            LDSM_X4(af, aOff + o);
#pragma unroll
            for (int j = 0; j < 4; j++) {
                int jp = j >> 1, idx = j & 1;
                MMA_F16(acc[i][j], af, bh[jp * 4 + idx], bh[jp * 4 + idx + 2]);
                MMA_F16(acc[i][j], af, bl[jp * 4 + idx], bl[jp * 4 + idx + 2]);
            }
        }
    }
}

__device__ __forceinline__ void compute_single(uint32_t sbase, int stage,
                                               int wm, int wn, int lane,
                                               float acc[4][4][4]) {
    uint32_t aOff = sbase + stage * ST2_STRIDE + ST_A;
    uint32_t bOff = sbase + stage * ST2_STRIDE + ST_BH;
    int lr = lane & 15, lh = lane >> 4;
#pragma unroll
    for (int ks = 0; ks < 2; ks++) {
        uint32_t bh[8];
#pragma unroll
        for (int jp = 0; jp < 2; jp++) {
            uint32_t o = sw64((uint32_t)(wn * 32 + jp * 16 + lr) * 64 + ks * 32 + lh * 16);
            LDSM_X4(&bh[jp * 4], bOff + o);
        }
#pragma unroll
        for (int i = 0; i < 4; i++) {
            uint32_t o = sw64((uint32_t)(wm * 64 + i * 16 + lr) * 64 + ks * 32 + lh * 16);
            uint32_t af[4];
            LDSM_X4(af, aOff + o);
#pragma unroll
            for (int j = 0; j < 4; j++) {
                int jp = j >> 1, idx = j & 1;
                MMA_F16(acc[i][j], af, bh[jp * 4 + idx], bh[jp * 4 + idx + 2]);
            }
        }
    }
}

// ---------------- K5: GEMM1 + SiLU*mul -> act fp16 ----------------
__global__ __launch_bounds__(256, 2) void k_mm1(const float* __restrict__ b1) {
    int tile = blockIdx.x;
    if (tile >= g_toff[NE]) return;
    int e = 0;
    while (tile >= g_toff[e + 1]) e++;
    int m0 = (tile - g_toff[e]) * TM;
    int cnt = g_cnt[e];
    int f0 = blockIdx.y * 64;
    int abase = e * NTOK + m0;   // row base into g_x / g_a

    extern __shared__ __align__(1024) char dsm[];
    __shared__ float sb1a[64], sb1g[64];
    uint32_t sbase = smem_u32(dsm);

    int tid = threadIdx.x, wid = tid >> 5, lane = tid & 31;
    int wm = wid >> 2, wn = wid & 3;

    if (tid < 64)       sb1a[tid] = b1[(size_t)e * 2 * DFFV + f0 + tid];
    else if (tid < 128) sb1g[tid - 64] = b1[(size_t)e * 2 * DFFV + DFFV + f0 + tid - 64];

    const __half* w1h = g_w1h + (size_t)e * 2 * DFFV * DIM;
    const __half* w1l = g_w1l + (size_t)e * 2 * DFFV * DIM;

    float acc[4][4][4];
#pragma unroll
    for (int i = 0; i < 4; i++)
#pragma unroll
        for (int j = 0; j < 4; j++)
#pragma unroll
            for (int q = 0; q < 4; q++) acc[i][j][q] = 0.f;

    auto load_chunk = [&](int stage, int c) {
        uint32_t base = sbase + stage * ST1_STRIDE;
        int k0 = c * 32;
#pragma unroll
        for (int u = tid; u < 512; u += 256) {
            int r = u >> 2, cs = u & 3;
            uint32_t sw = sw64((uint32_t)r * 64 + cs * 16);
            CPA16(base + ST_A + sw, g_x + (size_t)(abase + r) * DIM + k0 + cs * 8);
            int nw = (r & 1) ? (DFFV + f0 + (r >> 1)) : (f0 + (r >> 1));
            size_t gb = (size_t)nw * DIM + k0 + cs * 8;
            CPA16(base + ST_BH + sw, w1h + gb);
            CPA16(base + ST_BL + sw, w1l + gb);
        }
    };

    const int NC = DIM / 32;  // 16
    load_chunk(0, 0); CPA_COMMIT();
    load_chunk(1, 1); CPA_COMMIT();
    CPA_WAIT1();
    __syncthreads();
    for (int c = 0; c < NC; c++) {
        if (c + 2 < NC) load_chunk((c + 2) % NSTAGE, c + 2);
        CPA_COMMIT();
        compute_dual(sbase, c % NSTAGE, wm, wn, lane, acc);
        CPA_WAIT1();
        __syncthreads();
    }

    // bias + silu*mul in registers
#pragma unroll
    for (int i = 0; i < 4; i++)
#pragma unroll
        for (int j = 0; j < 4; j++) {
            int fl = wn * 16 + j * 4 + (lane & 3);
            float ba = sb1a[fl], bg = sb1g[fl];
            float a0 = acc[i][j][0] + ba, gg0 = acc[i][j][1] + bg;
            float a1 = acc[i][j][2] + ba, gg1 = acc[i][j][3] + bg;
            acc[i][j][0] = gg0 * a0 / (1.f + __expf(-a0));
            acc[i][j][2] = gg1 * a1 / (1.f + __expf(-a1));
        }

    // staged store through smem [128][72] halfs, 16B coalesced writes
    __half* st = (__half*)dsm;
#pragma unroll
    for (int i = 0; i < 4; i++) {
        int r0 = wm * 64 + i * 16 + (lane >> 2);
#pragma unroll
        for (int j = 0; j < 4; j++) {
            int fl = wn * 16 + j * 4 + (lane & 3);
            st[r0 * 72 + fl] = __float2half(acc[i][j][0]);
            st[(r0 + 8) * 72 + fl] = __float2half(acc[i][j][2]);
        }
    }
    __syncthreads();
#pragma unroll
    for (int u = tid; u < 1024; u += 256) {
        int r = u >> 3, seg = u & 7;
        if (m0 + r < cnt) {
            *(uint4*)(g_a + (size_t)(abase + r) * DFFV + f0 + seg * 8) =
                *(uint4*)&st[r * 72 + seg * 8];
        }
    }
}

// ---------------- K6: GEMM2 (single fp16 B) -> g_o ----------------
__global__ __launch_bounds__(256, 2) void k_mm2() {
    int tile = blockIdx.x;
    if (tile >= g_toff[NE]) return;
    int e = 0;
    while (tile >= g_toff[e + 1]) e++;
    int m0 = (tile - g_toff[e]) * TM;
    int cnt = g_cnt[e];
    int c0 = blockIdx.y * 128;
    int abase = e * NTOK + m0;

    extern __shared__ __align__(1024) char dsm[];
    uint32_t sbase = smem_u32(dsm);

    int tid = threadIdx.x, wid = tid >> 5, lane = tid & 31;
    int wm = wid >> 2, wn = wid & 3;

    const __half* w2 = g_w2 + (size_t)e * DIM * DFFV;

    float acc[4][4][4];
#pragma unroll
    for (int i = 0; i < 4; i++)
#pragma unroll
        for (int j = 0; j < 4; j++)
#pragma unroll
            for (int q = 0; q < 4; q++) acc[i][j][q] = 0.f;

    auto load_chunk = [&](int stage, int c) {
        uint32_t base = sbase + stage * ST2_STRIDE;
        int k0 = c * 32;
#pragma unroll
        for (int u = tid; u < 512; u += 256) {
            int r = u >> 2, cs = u & 3;
            uint32_t sw = sw64((uint32_t)r * 64 + cs * 16);
            CPA16(base + ST_A + sw, g_a + (size_t)(abase + r) * DFFV + k0 + cs * 8);
            CPA16(base + ST_BH + sw, w2 + (size_t)(c0 + r) * DFFV + k0 + cs * 8);
        }
    };

    const int NC = DFFV / 32;  // 32
    load_chunk(0, 0); CPA_COMMIT();
    load_chunk(1, 1); CPA_COMMIT();
    CPA_WAIT1();
    __syncthreads();
    for (int c = 0; c < NC; c++) {
        if (c + 2 < NC) load_chunk((c + 2) % NSTAGE, c + 2);
        CPA_COMMIT();
        compute_single(sbase, c % NSTAGE, wm, wn, lane, acc);
        CPA_WAIT1();
        __syncthreads();
    }

    // epilogue: raw float2 stores to g_o (no atomics)
#pragma unroll
    for (int i = 0; i < 4; i++) {
        int r0 = wm * 64 + i * 16 + (lane >> 2);
        int r1 = r0 + 8;
#pragma unroll
        for (int j = 0; j < 4; j++) {
            int nl = wn * 32 + j * 8 + (lane & 3) * 2;
            if (m0 + r0 < cnt) {
                float2 v = make_float2(acc[i][j][0], acc[i][j][1]);
                *(float2*)(g_o + (size_t)(abase + r0) * DIM + c0 + nl) = v;
            }
            if (m0 + r1 < cnt) {
                float2 v = make_float2(acc[i][j][2], acc[i][j][3]);
                *(float2*)(g_o + (size_t)(abase + r1) * DIM + c0 + nl) = v;
            }
        }
    }
}

// ---------------- K7: combine two expert rows per token ----------------
__global__ __launch_bounds__(256) void k_comb(const float* __restrict__ b2,
                                              float* __restrict__ out) {
    int tok = blockIdx.x * 2 + (threadIdx.x >> 7);
    int c = (threadIdx.x & 127) * 4;
    int id1 = g_pair[2 * tok], id2 = g_pair[2 * tok + 1];
    float w1 = g_wt[2 * tok], w2 = g_wt[2 * tok + 1];
    int e1 = id1 >> 13, e2 = id2 >> 13;   // NTOK = 8192 = 2^13
    float4 o1 = *(const float4*)(g_o + (size_t)id1 * DIM + c);
    float4 o2 = *(const float4*)(g_o + (size_t)id2 * DIM + c);
    float4 ba = *(const float4*)(b2 + (size_t)e1 * DIM + c);
    float4 bb = *(const float4*)(b2 + (size_t)e2 * DIM + c);
    float4 r;
    r.x = w1 * (o1.x + ba.x) + w2 * (o2.x + bb.x);
    r.y = w1 * (o1.y + ba.y) + w2 * (o2.y + bb.y);
    r.z = w1 * (o1.z + ba.z) + w2 * (o2.z + bb.z);
    r.w = w1 * (o1.w + ba.w) + w2 * (o2.w + bb.w);
    *(float4*)(out + (size_t)tok * DIM + c) = r;
}

// ---------------- launcher ----------------
extern "C" void kernel_launch(void* const* d_in, const int* in_sizes, int n_in,
                              void* d_out, int out_size) {
    const float* x  = (const float*)d_in[0];
    const float* Wg = (const float*)d_in[1];
    const float* bg = (const float*)d_in[2];
    const float* W1 = (const float*)d_in[3];
    const float* b1 = (const float*)d_in[4];
    const float* W2 = (const float*)d_in[5];
    const float* b2 = (const float*)d_in[6];
    float* out = (float*)d_out;

    const int SMEM1 = NSTAGE * ST1_STRIDE;  // 72 KB
    const int SMEM2 = NSTAGE * ST2_STRIDE;  // 48 KB
    cudaFuncSetAttribute(k_mm1, cudaFuncAttributeMaxDynamicSharedMemorySize, SMEM1);
    cudaFuncSetAttribute(k_mm2, cudaFuncAttributeMaxDynamicSharedMemorySize, SMEM2);

    k_zero<<<1, 32>>>();
    k_conv_w1<<<dim3(64, 16, NE), dim3(32, 8)>>>(W1);
    k_conv_w2<<<dim3(16, 32, NE), dim3(32, 8)>>>(W2);
    k_gate<<<NTOK / 8, 256>>>(x, Wg, bg);
    k_scan<<<1, 1>>>();
    k_mm1<<<dim3(MAXTILES, DFFV / 64), 256, SMEM1>>>(b1);
    k_mm2<<<dim3(MAXTILES, DIM / 128), 256, SMEM2>>>();
    k_comb<<<NTOK / 2, 256>>>(b2, out);
}

// round 10
// speedup vs baseline: 4.8259x; 1.4241x over previous
#include <cuda_runtime.h>
#include <cuda_fp16.h>
#include <math.h>
#include <stdint.h>

#define NTOK 8192
#define DIM 512
#define DFFV 1024
#define NE 8
#define TM 128
#define MAXTILES 136

// ---------------- device scratch ----------------
__device__ int   g_cnt[NE];
__device__ int   g_toff[NE + 1];
__device__ int   g_pair[2 * NTOK];        // token -> (id1, id2)
__device__ float g_wt  [2 * NTOK];        // token -> (w1, w2)
__device__ __half g_x  [(size_t)NE * NTOK * DIM];       // gathered x fp16
__device__ __half g_w1 [(size_t)NE * 2 * DFFV * DIM];   // W1^T fp16
__device__ __half g_w2 [(size_t)NE * DIM * DFFV];       // W2^T fp16
__device__ __half g_a  [(size_t)NE * NTOK * DFFV];      // act fp16
__device__ float  g_o  [(size_t)NE * NTOK * DIM];       // raw GEMM2 out

// ---------------- helpers ----------------
__device__ __forceinline__ uint32_t smem_u32(const void* p) {
    uint32_t a;
    asm("{ .reg .u64 t; cvta.to.shared.u64 t, %1; cvt.u32.u64 %0, t; }" : "=r"(a) : "l"(p));
    return a;
}
#define CPA16(sa, ga) asm volatile("cp.async.cg.shared.global [%0], [%1], 16;"::"r"(sa),"l"(ga):"memory")
#define CPA_COMMIT()  asm volatile("cp.async.commit_group;":::"memory")
#define CPA_WAIT2()   asm volatile("cp.async.wait_group 2;":::"memory")

#define LDSM_X4(r, addr) \
    asm volatile("ldmatrix.sync.aligned.m8n8.x4.shared.b16 {%0,%1,%2,%3}, [%4];" \
        : "=r"((r)[0]), "=r"((r)[1]), "=r"((r)[2]), "=r"((r)[3]) : "r"(addr))

#define MMA_F16(d, a, b0, b1) \
    asm volatile("mma.sync.aligned.m16n8k16.row.col.f32.f16.f16.f32 " \
        "{%0,%1,%2,%3},{%4,%5,%6,%7},{%8,%9},{%0,%1,%2,%3};" \
        : "+f"((d)[0]), "+f"((d)[1]), "+f"((d)[2]), "+f"((d)[3]) \
        : "r"((a)[0]), "r"((a)[1]), "r"((a)[2]), "r"((a)[3]), "r"(b0), "r"(b1))

__device__ __forceinline__ uint32_t sw64(uint32_t off) {
    return off ^ ((off >> 3) & 0x30);
}

// ---------------- K0: zero counters ----------------
__global__ void k_zero() {
    if (threadIdx.x < NE) g_cnt[threadIdx.x] = 0;
}

// ---------------- K1: gating + fused x->fp16 scatter ----------------
__global__ __launch_bounds__(256) void k_gate(const float* __restrict__ x,
                                              const float* __restrict__ Wg,
                                              const float* __restrict__ bg) {
    __shared__ float wgsT[NE][DIM];
    int t = threadIdx.x;
    for (int i = t; i < DIM * NE; i += 256) wgsT[i & 7][i >> 3] = Wg[i];
    __syncthreads();

    int warp = t >> 5, lane = t & 31;
    int tok = blockIdx.x * 8 + warp;

    float acc[NE];
#pragma unroll
    for (int e = 0; e < NE; e++) acc[e] = 0.f;
    const float4* xr = (const float4*)(x + (size_t)tok * DIM);
    float4 xv[4];
#pragma unroll
    for (int j = 0; j < 4; j++) {
        xv[j] = xr[lane + j * 32];
        int d = (lane + j * 32) * 4;
#pragma unroll
        for (int e = 0; e < NE; e++) {
            float4 w = *(const float4*)&wgsT[e][d];
            acc[e] += xv[j].x * w.x + xv[j].y * w.y + xv[j].z * w.z + xv[j].w * w.w;
        }
    }
#pragma unroll
    for (int e = 0; e < NE; e++)
#pragma unroll
        for (int o = 16; o; o >>= 1) acc[e] += __shfl_xor_sync(0xFFFFFFFFu, acc[e], o);

    int id1 = 0, id2 = 0;
    if (lane == 0) {
        float lg[NE];
#pragma unroll
        for (int e = 0; e < NE; e++) lg[e] = acc[e] + bg[e];
        int i1 = 0;
#pragma unroll
        for (int e = 1; e < NE; e++) if (lg[e] > lg[i1]) i1 = e;
        int i2 = (i1 == 0) ? 1 : 0;
#pragma unroll
        for (int e = 0; e < NE; e++) if (e != i1 && lg[e] > lg[i2]) i2 = e;
        float tt = expf(lg[i2] - lg[i1]);
        float w1 = 1.f / (1.f + tt);
        float w2 = tt / (1.f + tt);
        int p1 = atomicAdd(&g_cnt[i1], 1);
        int p2 = atomicAdd(&g_cnt[i2], 1);
        id1 = i1 * NTOK + p1;
        id2 = i2 * NTOK + p2;
        g_pair[2 * tok] = id1; g_pair[2 * tok + 1] = id2;
        g_wt[2 * tok] = w1;    g_wt[2 * tok + 1] = w2;
    }
    id1 = __shfl_sync(0xFFFFFFFFu, id1, 0);
    id2 = __shfl_sync(0xFFFFFFFFu, id2, 0);

#pragma unroll
    for (int j = 0; j < 4; j++) {
        __half h[4] = {__float2half(xv[j].x), __float2half(xv[j].y),
                       __float2half(xv[j].z), __float2half(xv[j].w)};
        int c = (lane + j * 32) * 4;
        *(uint2*)(g_x + (size_t)id1 * DIM + c) = *(uint2*)h;
        *(uint2*)(g_x + (size_t)id2 * DIM + c) = *(uint2*)h;
    }
}

// ---------------- K2: tile scan ----------------
__global__ void k_scan() {
    int tt = 0;
    for (int e = 0; e < NE; e++) {
        g_toff[e] = tt;
        tt += (g_cnt[e] + TM - 1) / TM;
    }
    g_toff[NE] = tt;
}

// ---------------- K3/K4: weight transpose + single fp16 ----------------
__global__ void k_conv_w1(const float* __restrict__ W1) {
    __shared__ float ts[32][33];
    int e = blockIdx.z, n0 = blockIdx.x * 32, k0 = blockIdx.y * 32;
    int tx = threadIdx.x, ty = threadIdx.y;
    const float* src = W1 + (size_t)e * DIM * 2 * DFFV;
#pragma unroll
    for (int i = 0; i < 4; i++)
        ts[ty + i * 8][tx] = src[(size_t)(k0 + ty + i * 8) * 2 * DFFV + n0 + tx];
    __syncthreads();
#pragma unroll
    for (int i = 0; i < 4; i++) {
        float v = ts[tx][ty + i * 8];
        size_t o = (size_t)e * 2 * DFFV * DIM + (size_t)(n0 + ty + i * 8) * DIM + k0 + tx;
        g_w1[o] = __float2half(v);
    }
}
__global__ void k_conv_w2(const float* __restrict__ W2) {
    __shared__ float ts[32][33];
    int e = blockIdx.z, d0 = blockIdx.x * 32, f0 = blockIdx.y * 32;
    int tx = threadIdx.x, ty = threadIdx.y;
    const float* src = W2 + (size_t)e * DFFV * DIM;
#pragma unroll
    for (int i = 0; i < 4; i++)
        ts[ty + i * 8][tx] = src[(size_t)(f0 + ty + i * 8) * DIM + d0 + tx];
    __syncthreads();
#pragma unroll
    for (int i = 0; i < 4; i++) {
        float v = ts[tx][ty + i * 8];
        size_t o = (size_t)e * DIM * DFFV + (size_t)(d0 + ty + i * 8) * DFFV + f0 + tx;
        g_w2[o] = __float2half(v);
    }
}

// ==================== GEMM core (single x single fp16) ====================
// tile 128x128, BK=32, 4 stages, wait_group 2, 8 warps (2x4), warp tile 64x32
#define ST_A  0
#define ST_B  8192
#define ST_STRIDE 16384
#define NSTAGE 4

__device__ __forceinline__ void compute_chunk(uint32_t sbase, int stage,
                                              int wm, int wn, int lane,
                                              float acc[4][4][4]) {
    uint32_t aOff = sbase + stage * ST_STRIDE + ST_A;
    uint32_t bOff = sbase + stage * ST_STRIDE + ST_B;
    int lr = lane & 15, lh = lane >> 4;
#pragma unroll
    for (int ks = 0; ks < 2; ks++) {
        uint32_t bh[8];
#pragma unroll
        for (int jp = 0; jp < 2; jp++) {
            uint32_t o = sw64((uint32_t)(wn * 32 + jp * 16 + lr) * 64 + ks * 32 + lh * 16);
            LDSM_X4(&bh[jp * 4], bOff + o);
        }
#pragma unroll
        for (int i = 0; i < 4; i++) {
            uint32_t o = sw64((uint32_t)(wm * 64 + i * 16 + lr) * 64 + ks * 32 + lh * 16);
            uint32_t af[4];
            LDSM_X4(af, aOff + o);
#pragma unroll
            for (int j = 0; j < 4; j++) {
                int jp = j >> 1, idx = j & 1;
                MMA_F16(acc[i][j], af, bh[jp * 4 + idx], bh[jp * 4 + idx + 2]);
            }
        }
    }
}

// ---------------- K5: GEMM1 + SiLU*mul -> act fp16 ----------------
__global__ __launch_bounds__(256, 2) void k_mm1(const float* __restrict__ b1) {
    int tile = blockIdx.x;
    if (tile >= g_toff[NE]) return;
    int e = 0;
    while (tile >= g_toff[e + 1]) e++;
    int m0 = (tile - g_toff[e]) * TM;
    int cnt = g_cnt[e];
    int f0 = blockIdx.y * 64;
    int abase = e * NTOK + m0;

    extern __shared__ __align__(1024) char dsm[];
    __shared__ float sb1a[64], sb1g[64];
    uint32_t sbase = smem_u32(dsm);

    int tid = threadIdx.x, wid = tid >> 5, lane = tid & 31;
    int wm = wid >> 2, wn = wid & 3;

    if (tid < 64)       sb1a[tid] = b1[(size_t)e * 2 * DFFV + f0 + tid];
    else if (tid < 128) sb1g[tid - 64] = b1[(size_t)e * 2 * DFFV + DFFV + f0 + tid - 64];

    const __half* w1 = g_w1 + (size_t)e * 2 * DFFV * DIM;

    float acc[4][4][4];
#pragma unroll
    for (int i = 0; i < 4; i++)
#pragma unroll
        for (int j = 0; j < 4; j++)
#pragma unroll
            for (int q = 0; q < 4; q++) acc[i][j][q] = 0.f;

    auto load_chunk = [&](int stage, int c) {
        uint32_t base = sbase + stage * ST_STRIDE;
        int k0 = c * 32;
#pragma unroll
        for (int u = tid; u < 512; u += 256) {
            int r = u >> 2, cs = u & 3;
            uint32_t sw = sw64((uint32_t)r * 64 + cs * 16);
            CPA16(base + ST_A + sw, g_x + (size_t)(abase + r) * DIM + k0 + cs * 8);
            int nw = (r & 1) ? (DFFV + f0 + (r >> 1)) : (f0 + (r >> 1));
            CPA16(base + ST_B + sw, w1 + (size_t)nw * DIM + k0 + cs * 8);
        }
    };

    const int NC = DIM / 32;  // 16
    load_chunk(0, 0); CPA_COMMIT();
    load_chunk(1, 1); CPA_COMMIT();
    load_chunk(2, 2); CPA_COMMIT();
    CPA_WAIT2();
    __syncthreads();
    for (int c = 0; c < NC; c++) {
        if (c + 3 < NC) load_chunk((c + 3) % NSTAGE, c + 3);
        CPA_COMMIT();
        compute_chunk(sbase, c % NSTAGE, wm, wn, lane, acc);
        CPA_WAIT2();
        __syncthreads();
    }

    // bias + silu*mul in registers
#pragma unroll
    for (int i = 0; i < 4; i++)
#pragma unroll
        for (int j = 0; j < 4; j++) {
            int fl = wn * 16 + j * 4 + (lane & 3);
            float ba = sb1a[fl], bg = sb1g[fl];
            float a0 = acc[i][j][0] + ba, gg0 = acc[i][j][1] + bg;
            float a1 = acc[i][j][2] + ba, gg1 = acc[i][j][3] + bg;
            acc[i][j][0] = gg0 * a0 / (1.f + __expf(-a0));
            acc[i][j][2] = gg1 * a1 / (1.f + __expf(-a1));
        }

    // staged store through smem [128][72] halfs, 16B coalesced writes
    __half* st = (__half*)dsm;
#pragma unroll
    for (int i = 0; i < 4; i++) {
        int r0 = wm * 64 + i * 16 + (lane >> 2);
#pragma unroll
        for (int j = 0; j < 4; j++) {
            int fl = wn * 16 + j * 4 + (lane & 3);
            st[r0 * 72 + fl] = __float2half(acc[i][j][0]);
            st[(r0 + 8) * 72 + fl] = __float2half(acc[i][j][2]);
        }
    }
    __syncthreads();
#pragma unroll
    for (int u = tid; u < 1024; u += 256) {
        int r = u >> 3, seg = u & 7;
        if (m0 + r < cnt) {
            *(uint4*)(g_a + (size_t)(abase + r) * DFFV + f0 + seg * 8) =
                *(uint4*)&st[r * 72 + seg * 8];
        }
    }
}

// ---------------- K6: GEMM2 (single fp16) -> g_o ----------------
__global__ __launch_bounds__(256, 2) void k_mm2() {
    int tile = blockIdx.x;
    if (tile >= g_toff[NE]) return;
    int e = 0;
    while (tile >= g_toff[e + 1]) e++;
    int m0 = (tile - g_toff[e]) * TM;
    int cnt = g_cnt[e];
    int c0 = blockIdx.y * 128;
    int abase = e * NTOK + m0;

    extern __shared__ __align__(1024) char dsm[];
    uint32_t sbase = smem_u32(dsm);

    int tid = threadIdx.x, wid = tid >> 5, lane = tid & 31;
    int wm = wid >> 2, wn = wid & 3;

    const __half* w2 = g_w2 + (size_t)e * DIM * DFFV;

    float acc[4][4][4];
#pragma unroll
    for (int i = 0; i < 4; i++)
#pragma unroll
        for (int j = 0; j < 4; j++)
#pragma unroll
            for (int q = 0; q < 4; q++) acc[i][j][q] = 0.f;

    auto load_chunk = [&](int stage, int c) {
        uint32_t base = sbase + stage * ST_STRIDE;
        int k0 = c * 32;
#pragma unroll
        for (int u = tid; u < 512; u += 256) {
            int r = u >> 2, cs = u & 3;
            uint32_t sw = sw64((uint32_t)r * 64 + cs * 16);
            CPA16(base + ST_A + sw, g_a + (size_t)(abase + r) * DFFV + k0 + cs * 8);
            CPA16(base + ST_B + sw, w2 + (size_t)(c0 + r) * DFFV + k0 + cs * 8);
        }
    };

    const int NC = DFFV / 32;  // 32
    load_chunk(0, 0); CPA_COMMIT();
    load_chunk(1, 1); CPA_COMMIT();
    load_chunk(2, 2); CPA_COMMIT();
    CPA_WAIT2();
    __syncthreads();
    for (int c = 0; c < NC; c++) {
        if (c + 3 < NC) load_chunk((c + 3) % NSTAGE, c + 3);
        CPA_COMMIT();
        compute_chunk(sbase, c % NSTAGE, wm, wn, lane, acc);
        CPA_WAIT2();
        __syncthreads();
    }

    // epilogue: raw float2 stores to g_o (no atomics)
#pragma unroll
    for (int i = 0; i < 4; i++) {
        int r0 = wm * 64 + i * 16 + (lane >> 2);
        int r1 = r0 + 8;
#pragma unroll
        for (int j = 0; j < 4; j++) {
            int nl = wn * 32 + j * 8 + (lane & 3) * 2;
            if (m0 + r0 < cnt) {
                float2 v = make_float2(acc[i][j][0], acc[i][j][1]);
                *(float2*)(g_o + (size_t)(abase + r0) * DIM + c0 + nl) = v;
            }
            if (m0 + r1 < cnt) {
                float2 v = make_float2(acc[i][j][2], acc[i][j][3]);
                *(float2*)(g_o + (size_t)(abase + r1) * DIM + c0 + nl) = v;
            }
        }
    }
}

// ---------------- K7: combine two expert rows per token ----------------
__global__ __launch_bounds__(256) void k_comb(const float* __restrict__ b2,
                                              float* __restrict__ out) {
    int tok = blockIdx.x * 2 + (threadIdx.x >> 7);
    int c = (threadIdx.x & 127) * 4;
    int id1 = g_pair[2 * tok], id2 = g_pair[2 * tok + 1];
    float w1 = g_wt[2 * tok], w2 = g_wt[2 * tok + 1];
    int e1 = id1 >> 13, e2 = id2 >> 13;
    float4 o1 = *(const float4*)(g_o + (size_t)id1 * DIM + c);
    float4 o2 = *(const float4*)(g_o + (size_t)id2 * DIM + c);
    float4 ba = *(const float4*)(b2 + (size_t)e1 * DIM + c);
    float4 bb = *(const float4*)(b2 + (size_t)e2 * DIM + c);
    float4 r;
    r.x = w1 * (o1.x + ba.x) + w2 * (o2.x + bb.x);
    r.y = w1 * (o1.y + ba.y) + w2 * (o2.y + bb.y);
    r.z = w1 * (o1.z + ba.z) + w2 * (o2.z + bb.z);
    r.w = w1 * (o1.w + ba.w) + w2 * (o2.w + bb.w);
    *(float4*)(out + (size_t)tok * DIM + c) = r;
}

// ---------------- launcher ----------------
extern "C" void kernel_launch(void* const* d_in, const int* in_sizes, int n_in,
                              void* d_out, int out_size) {
    const float* x  = (const float*)d_in[0];
    const float* Wg = (const float*)d_in[1];
    const float* bg = (const float*)d_in[2];
    const float* W1 = (const float*)d_in[3];
    const float* b1 = (const float*)d_in[4];
    const float* W2 = (const float*)d_in[5];
    const float* b2 = (const float*)d_in[6];
    float* out = (float*)d_out;

    const int SMEM = NSTAGE * ST_STRIDE;  // 64 KB
    cudaFuncSetAttribute(k_mm1, cudaFuncAttributeMaxDynamicSharedMemorySize, SMEM);
    cudaFuncSetAttribute(k_mm2, cudaFuncAttributeMaxDynamicSharedMemorySize, SMEM);

    k_zero<<<1, 32>>>();
    k_conv_w1<<<dim3(64, 16, NE), dim3(32, 8)>>>(W1);
    k_conv_w2<<<dim3(16, 32, NE), dim3(32, 8)>>>(W2);
    k_gate<<<NTOK / 8, 256>>>(x, Wg, bg);
    k_scan<<<1, 1>>>();
    k_mm1<<<dim3(MAXTILES, DFFV / 64), 256, SMEM>>>(b1);
    k_mm2<<<dim3(MAXTILES, DIM / 128), 256, SMEM>>>();
    k_comb<<<NTOK / 2, 256>>>(b2, out);
}